// round 15
// baseline (speedup 1.0000x reference)
#include <cuda_runtime.h>
#include <cuda_bf16.h>
#include <cuda_fp16.h>
#include <cuda_fp8.h>
#include <math.h>

// Problem constants
#define BB 2
#define NA 64
#define NL 256
#define NN 320          // N = NA + NL
#define DD 128
#define HH 8
#define HDD 16
#define LL 3
#define TT 50
#define NPAIR (BB*NN*NN)     // 204800
#define SP 321               // padded score stride (bank-conflict-free)

#define QKOFF  (3*384*128)                  // 147456
#define FC2OFF (QKOFF + 3*512*128)          // 344064
#define WTOT   (FC2OFF + 3*128*512)         // 540672

// ---------------- device scratch ----------------
__device__ float g_pf[BB*NN*3];
__device__ unsigned char g_rp8 [NPAIR*DD];  // rel_pos      fp8 e4m3
__device__ unsigned char g_rpn8[NPAIR*DD];  // rel_pos_neg  fp8 e4m3
__device__ __half g_w2t[2][DD*DD];    // relmlp W2^T fp16
__device__ __half g_wT[WTOT];         // qkv/fc1/fc2 weights, fp16, [n][k]
__device__ float g_x  [BB*NN*DD];
__device__ __half g_qh [BB*NN*DD];    // q fp16
__device__ __half g_kvh[BB*NN*256];   // k (0:128) | v (128:256) fp16
__device__ __half g_hidh[BB*NN*4*DD]; // fc1 hidden, fp16

__device__ __forceinline__ __half2 fp8x2_to_h2(__nv_fp8x2_storage_t v) {
    __half2_raw hr = __nv_cvt_fp8x2_to_halfraw2(v, __NV_E4M3);
    return *reinterpret_cast<__half2*>(&hr);
}

// ---------------- fused prep: pf + W2^T + initx + weightsT, one launch ----------------
__global__ void prep_kernel(const float* __restrict__ xpos,
                            const float* __restrict__ xang,
                            const float* __restrict__ lpos,
                            const float* __restrict__ pw2,
                            const float* __restrict__ nw2,
                            const float* __restrict__ agent,
                            const float* __restrict__ lane,
                            const float* __restrict__ qkvw,
                            const float* __restrict__ fc1w,
                            const float* __restrict__ fc2w) {
    int blk = blockIdx.x;
    int t = threadIdx.x;
    if (blk < 3) {                       // pose features: 640 items
        int i = blk * 256 + t;
        if (i >= BB*NN) return;
        int b = i / NN, n = i % NN;
        float px, py, pa;
        if (n < NA) {
            int base = ((b*NA + n)*TT + 49) * 2;
            px = xpos[base]; py = xpos[base+1];
            pa = xang[(b*NA + n)*TT + 49];
        } else {
            int l = n - NA;
            int base = (b*NL + l) * 20 * 2;
            px = lpos[base]; py = lpos[base+1];
            float x1 = lpos[base+2], y1 = lpos[base+3];
            pa = atan2f(y1 - py, x1 - px);
        }
        g_pf[i*3+0] = px; g_pf[i*3+1] = py; g_pf[i*3+2] = pa;
    } else if (blk < 3 + 128) {          // relmlp W2 transpose: 32768 items
        int idx = (blk - 3) * 256 + t;
        int s = idx >> 14;
        int r = idx & 16383;
        int n = r >> 7, k = r & 127;
        const float* W2 = s ? nw2 : pw2;
        g_w2t[s][n*DD + k] = __float2half(W2[k*DD + n]);
    } else if (blk < 3 + 128 + 320) {    // initx: 81920 items
        int i = (blk - 131) * 256 + t;
        if (i >= BB*NN*DD) return;
        int d = i & 127;
        int bn = i >> 7;
        int b = bn / NN, n = bn % NN;
        g_x[i] = (n < NA) ? agent[(b*NA + n)*DD + d]
                          : lane [(b*NL + (n - NA))*DD + d];
    } else if (blk < 451 + 576) {        // qkvw^T: 147456 items
        int idx = (blk - 451) * 256 + t;
        int l = idx / 49152, r = idx % 49152;
        int n = r >> 7, k = r & 127;
        g_wT[idx] = __float2half(qkvw[(size_t)l*49152 + k*384 + n]);
    } else if (blk < 451 + 576 + 768) {  // fc1w^T: 196608 items
        int idx = (blk - 1027) * 256 + t;
        int l = idx >> 16, r = idx & 65535;
        int n = r >> 7, k = r & 127;
        g_wT[QKOFF + idx] = __float2half(fc1w[(size_t)l*65536 + k*512 + n]);
    } else {                             // fc2w^T: 196608 items
        int idx = (blk - 1795) * 256 + t;
        int l = idx >> 16, r = idx & 65535;
        int n = r / 512, k = r % 512;
        g_wT[FC2OFF + idx] = __float2half(fc2w[(size_t)l*65536 + k*128 + n]);
    }
}

// ---------------- MMA / ldmatrix helpers ----------------
__device__ __forceinline__ void mma_f16(float& d0, float& d1, float& d2, float& d3,
                                        unsigned a0, unsigned a1, unsigned a2, unsigned a3,
                                        unsigned b0, unsigned b1) {
    asm volatile(
        "mma.sync.aligned.m16n8k16.row.col.f32.f16.f16.f32 "
        "{%0,%1,%2,%3}, {%4,%5,%6,%7}, {%8,%9}, {%0,%1,%2,%3};"
        : "+f"(d0), "+f"(d1), "+f"(d2), "+f"(d3)
        : "r"(a0), "r"(a1), "r"(a2), "r"(a3), "r"(b0), "r"(b1));
}

__device__ __forceinline__ void ldsm_x4(unsigned& d0, unsigned& d1,
                                        unsigned& d2, unsigned& d3, unsigned addr) {
    asm volatile("ldmatrix.sync.aligned.m8n8.x4.shared.b16 {%0,%1,%2,%3}, [%4];"
        : "=r"(d0), "=r"(d1), "=r"(d2), "=r"(d3) : "r"(addr));
}

__device__ __forceinline__ unsigned pack2(float lo, float hi) {
    __half2 h = __floats2half2_rn(lo, hi);
    return *reinterpret_cast<unsigned*>(&h);
}

// ---------------- rel-pos MLP: half2 hidden + fp16 MMA (ldmatrix B), fp8 output ----------------
__global__ __launch_bounds__(512) void relmlp_kernel(
    const float* __restrict__ pw1, const float* __restrict__ pb1,
    const float* __restrict__ pb2,
    const float* __restrict__ nw1, const float* __restrict__ nb1,
    const float* __restrict__ nb2)
{
    const int sign = blockIdx.y;                 // 0 = pos, 1 = neg
    const float* W1 = sign ? nw1 : pw1;
    const float* B1 = sign ? nb1 : pb1;
    const float* B2 = sign ? nb2 : pb2;
    unsigned char* out = sign ? g_rpn8 : g_rp8;

    __shared__ __half2 w1h[4][64];               // packed fp16 W1 [j][kpair]
    __shared__ __half2 b1h[64];
    __shared__ float b2_s[128];
    __shared__ float rel_s[128][4];
    __shared__ __half2 w2t_s[128][68];           // [n][kpair]; rows 272B, 16B-aligned

    int tid = threadIdx.x;
    int warp = tid >> 5, lane = tid & 31;
    int mg = warp >> 1, nh = warp & 1;
    int r0 = lane >> 2, cq = lane & 3;
    int mb = mg * 16;

    if (tid < 128) {
        b2_s[tid] = B2[tid];
        int p = blockIdx.x * 128 + tid;
        int b = p / (NN*NN);
        int r = p - b*(NN*NN);
        int n = r / NN;
        int m = r - n*NN;
        const float* pn = g_pf + (b*NN + n)*3;
        const float* pm = g_pf + (b*NN + m)*3;
        float dx = pn[0]-pm[0], dy = pn[1]-pm[1];
        float dist = sqrtf(dx*dx + dy*dy);
        float ad = pn[2]-pm[2];
        float sg = sign ? -1.f : 1.f;
        rel_s[tid][0] = sg*dx; rel_s[tid][1] = sg*dy;
        rel_s[tid][2] = dist;  rel_s[tid][3] = sg*ad;
    } else if (tid < 448) {
        int u = tid - 128;           // 0..319
        int j = u >> 6, t = u & 63;
        if (j < 4)
            w1h[j][t] = __floats2half2_rn(W1[j*128 + 2*t], W1[j*128 + 2*t + 1]);
        else
            b1h[t] = __floats2half2_rn(B1[2*t], B1[2*t + 1]);
    }
    {
        const uint4* src = reinterpret_cast<const uint4*>(&g_w2t[sign][0]);
        for (int idx = tid; idx < 2048; idx += 512) {
            int n = idx >> 4, c = idx & 15;
            *reinterpret_cast<uint4*>(&w2t_s[n][c*4]) = src[idx];
        }
    }
    __syncthreads();

    // rel features as half2 broadcasts for the two rows this lane owns
    __half2 rA[4], rB[4];
    #pragma unroll
    for (int j = 0; j < 4; j++) {
        rA[j] = __float2half2_rn(rel_s[mb + r0    ][j]);
        rB[j] = __float2half2_rn(rel_s[mb + r0 + 8][j]);
    }

    // hidden layer directly into packed A-fragments (half2 math)
    unsigned ha[8][4];
    const __half2 zero2 = __floats2half2_rn(0.f, 0.f);
    #pragma unroll
    for (int s = 0; s < 8; s++) {
        #pragma unroll
        for (int pp = 0; pp < 2; pp++) {
            int t0 = s*8 + pp*4 + cq;
            __half2 w0 = w1h[0][t0], w1v = w1h[1][t0],
                    w2v = w1h[2][t0], w3v = w1h[3][t0];
            __half2 hb = b1h[t0];
            __half2 hA = __hfma2(rA[0], w0, hb);
            hA = __hfma2(rA[1], w1v, hA);
            hA = __hfma2(rA[2], w2v, hA);
            hA = __hfma2(rA[3], w3v, hA);
            __half2 hB = __hfma2(rB[0], w0, hb);
            hB = __hfma2(rB[1], w1v, hB);
            hB = __hfma2(rB[2], w2v, hB);
            hB = __hfma2(rB[3], w3v, hB);
            hA = __hmax2(hA, zero2);
            hB = __hmax2(hB, zero2);
            ha[s][pp*2 + 0] = *reinterpret_cast<unsigned*>(&hA);
            ha[s][pp*2 + 1] = *reinterpret_cast<unsigned*>(&hB);
        }
    }

    float acc[8][4];
    #pragma unroll
    for (int nt = 0; nt < 8; nt++)
        #pragma unroll
        for (int c = 0; c < 4; c++) acc[nt][c] = 0.f;

    // B fragments via ldmatrix.x4
    unsigned lbase;
    {
        unsigned sb = (unsigned)__cvta_generic_to_shared(&w2t_s[0][0]);
        int rowt = nh*64 + ((lane >> 4) & 1)*8 + (lane & 7);
        lbase = sb + rowt*272 + ((lane >> 3) & 1)*16;
    }
    #pragma unroll
    for (int s = 0; s < 8; s++) {
        #pragma unroll
        for (int g = 0; g < 4; g++) {
            unsigned b0, b1, b2v, b3;
            ldsm_x4(b0, b1, b2v, b3, lbase + g*(16*272) + s*32);
            mma_f16(acc[2*g][0], acc[2*g][1], acc[2*g][2], acc[2*g][3],
                    ha[s][0], ha[s][1], ha[s][2], ha[s][3], b0, b1);
            mma_f16(acc[2*g+1][0], acc[2*g+1][1], acc[2*g+1][2], acc[2*g+1][3],
                    ha[s][0], ha[s][1], ha[s][2], ha[s][3], b2v, b3);
        }
    }

    // epilogue: fp8-pack into reused smem, then bulk 16B stores
    __syncthreads();   // all MMA reads of w2t_s complete
    unsigned char* st8 = reinterpret_cast<unsigned char*>(w2t_s);
    #pragma unroll
    for (int nt = 0; nt < 8; nt++) {
        int col = nh*64 + nt*8 + 2*cq;
        float bi0 = b2_s[col], bi1 = b2_s[col+1];
        float2 f0 = make_float2(acc[nt][0] + bi0, acc[nt][1] + bi1);
        float2 f1 = make_float2(acc[nt][2] + bi0, acc[nt][3] + bi1);
        __nv_fp8x2_storage_t p0 = __nv_cvt_float2_to_fp8x2(f0, __NV_SATFINITE, __NV_E4M3);
        __nv_fp8x2_storage_t p1 = __nv_cvt_float2_to_fp8x2(f1, __NV_SATFINITE, __NV_E4M3);
        *reinterpret_cast<unsigned short*>(st8 + (mb + r0    )*128 + col) = p0;
        *reinterpret_cast<unsigned short*>(st8 + (mb + r0 + 8)*128 + col) = p1;
    }
    __syncthreads();
    {
        const uint4* src = reinterpret_cast<const uint4*>(st8);
        uint4* dst = reinterpret_cast<uint4*>(out + (size_t)blockIdx.x * 128 * 128);
        for (int idx = tid; idx < 1024; idx += 512)
            __stcs(dst + idx, src[idx]);
    }
}

// ---------------- fp16 tensor-core GEMM for the transformer chain ----------------
// MODE 0: qkv  = LN(A) @ W + b          -> g_qh / g_kvh (fp16)
// MODE 1: fc1  = relu(LN(A) @ W + b)    -> g_hidh (fp16)
// MODE 2: fc2  = g_hidh @ W + b + res   -> C (fp32), K=512
template<int MODE>
__global__ __launch_bounds__(256) void gemmh(
    const float* __restrict__ A, const __half* __restrict__ WT,
    const float* __restrict__ bias,
    const float* __restrict__ lng, const float* __restrict__ lnb,
    const float* __restrict__ res, float* __restrict__ C, int N)
{
    const int K = (MODE == 2) ? 512 : 128;
    __shared__ __half As_h[32][136];
    __shared__ __half Ws_h[64][136];
    __shared__ float bs_n[64];
    __shared__ float gs[128], bs[128];

    int tid = threadIdx.x;
    int warp = tid >> 5, lane = tid & 31;
    int r0 = lane >> 2, cq = lane & 3;
    int mg = warp >> 2, nh = warp & 3;
    int m0 = blockIdx.y * 32, n0 = blockIdx.x * 64;
    int mb = mg * 16;

    if (tid < 64) bs_n[tid] = bias[n0 + tid];
    if (MODE != 2 && tid >= 64 && tid < 192) {
        int t = tid - 64;
        gs[t] = lng[t]; bs[t] = lnb[t];
    }
    __syncthreads();

    float acc[2][4];
    #pragma unroll
    for (int nt = 0; nt < 2; nt++)
        #pragma unroll
        for (int c = 0; c < 4; c++) acc[nt][c] = 0.f;

    const int NCHUNK = (MODE == 2) ? 4 : 1;
    for (int kc = 0; kc < NCHUNK; kc++) {
        // ---- stage A tile ----
        if (MODE == 2) {
            for (int idx = tid; idx < 512; idx += 256) {
                int row = idx >> 4, c = idx & 15;
                uint4 v = *reinterpret_cast<const uint4*>(
                    g_hidh + (size_t)(m0 + row)*512 + kc*128 + c*8);
                const __half2* h2 = reinterpret_cast<const __half2*>(&v);
                __half2* dst = reinterpret_cast<__half2*>(&As_h[row][c*8]);
                dst[0] = h2[0]; dst[1] = h2[1]; dst[2] = h2[2]; dst[3] = h2[3];
            }
        } else {
            #pragma unroll
            for (int r = 0; r < 4; r++) {
                int row = warp*4 + r;
                float4 v = *reinterpret_cast<const float4*>(
                    A + (size_t)(m0 + row)*128 + lane*4);
                float s = v.x + v.y + v.z + v.w;
                #pragma unroll
                for (int o = 16; o; o >>= 1) s += __shfl_xor_sync(~0u, s, o);
                float mu = s * 0.0078125f;
                float d0 = v.x-mu, d1 = v.y-mu, d2 = v.z-mu, d3 = v.w-mu;
                float q = d0*d0 + d1*d1 + d2*d2 + d3*d3;
                #pragma unroll
                for (int o = 16; o; o >>= 1) q += __shfl_xor_sync(~0u, q, o);
                float rs = rsqrtf(q * 0.0078125f + 1e-5f);
                int c0 = lane*4;
                float y0 = d0*rs*gs[c0  ] + bs[c0  ];
                float y1 = d1*rs*gs[c0+1] + bs[c0+1];
                float y2 = d2*rs*gs[c0+2] + bs[c0+2];
                float y3 = d3*rs*gs[c0+3] + bs[c0+3];
                __half2* dst = reinterpret_cast<__half2*>(&As_h[row][c0]);
                dst[0] = __floats2half2_rn(y0, y1);
                dst[1] = __floats2half2_rn(y2, y3);
            }
        }
        for (int idx = tid; idx < 1024; idx += 256) {
            int n = idx >> 4, c = idx & 15;
            uint4 v = *reinterpret_cast<const uint4*>(
                WT + (size_t)(n0 + n)*K + kc*128 + c*8);
            const __half2* h2 = reinterpret_cast<const __half2*>(&v);
            __half2* dst = reinterpret_cast<__half2*>(&Ws_h[n][c*8]);
            dst[0] = h2[0]; dst[1] = h2[1]; dst[2] = h2[2]; dst[3] = h2[3];
        }
        __syncthreads();

        #pragma unroll
        for (int s = 0; s < 8; s++) {
            unsigned a0 = *reinterpret_cast<unsigned*>(&As_h[mb+r0  ][16*s + 2*cq]);
            unsigned a1 = *reinterpret_cast<unsigned*>(&As_h[mb+r0+8][16*s + 2*cq]);
            unsigned a2 = *reinterpret_cast<unsigned*>(&As_h[mb+r0  ][16*s + 2*cq + 8]);
            unsigned a3 = *reinterpret_cast<unsigned*>(&As_h[mb+r0+8][16*s + 2*cq + 8]);
            #pragma unroll
            for (int nt = 0; nt < 2; nt++) {
                int n = nh*16 + nt*8 + r0;
                unsigned b0 = *reinterpret_cast<unsigned*>(&Ws_h[n][16*s + 2*cq]);
                unsigned b1 = *reinterpret_cast<unsigned*>(&Ws_h[n][16*s + 2*cq + 8]);
                mma_f16(acc[nt][0], acc[nt][1], acc[nt][2], acc[nt][3],
                        a0, a1, a2, a3, b0, b1);
            }
        }
        __syncthreads();
    }

    // ---- epilogue ----
    #pragma unroll
    for (int nt = 0; nt < 2; nt++) {
        int nloc = nh*16 + nt*8 + 2*cq;
        int n = n0 + nloc;
        float bi0 = bs_n[nloc], bi1 = bs_n[nloc+1];
        int mA = m0 + mb + r0, mB = mA + 8;
        float c00 = acc[nt][0] + bi0, c01 = acc[nt][1] + bi1;
        float c10 = acc[nt][2] + bi0, c11 = acc[nt][3] + bi1;
        if (MODE == 0) {
            int seg = n >> 7, off = n & 127;
            __half2 hA = __floats2half2_rn(c00, c01);
            __half2 hB = __floats2half2_rn(c10, c11);
            if (seg == 0) {
                *reinterpret_cast<__half2*>(&g_qh[(size_t)mA*128 + off]) = hA;
                *reinterpret_cast<__half2*>(&g_qh[(size_t)mB*128 + off]) = hB;
            } else if (seg == 1) {
                *reinterpret_cast<__half2*>(&g_kvh[(size_t)mA*256 + off]) = hA;
                *reinterpret_cast<__half2*>(&g_kvh[(size_t)mB*256 + off]) = hB;
            } else {
                *reinterpret_cast<__half2*>(&g_kvh[(size_t)mA*256 + 128 + off]) = hA;
                *reinterpret_cast<__half2*>(&g_kvh[(size_t)mB*256 + 128 + off]) = hB;
            }
        } else if (MODE == 1) {
            __half2 hA = __floats2half2_rn(fmaxf(c00, 0.f), fmaxf(c01, 0.f));
            __half2 hB = __floats2half2_rn(fmaxf(c10, 0.f), fmaxf(c11, 0.f));
            *reinterpret_cast<__half2*>(&g_hidh[(size_t)mA*512 + n]) = hA;
            *reinterpret_cast<__half2*>(&g_hidh[(size_t)mB*512 + n]) = hB;
        } else {
            c00 += res[(size_t)mA*128 + n];
            c01 += res[(size_t)mA*128 + n + 1];
            c10 += res[(size_t)mB*128 + n];
            c11 += res[(size_t)mB*128 + n + 1];
            *reinterpret_cast<float2*>(&C[(size_t)mA*128 + n]) = make_float2(c00, c01);
            *reinterpret_cast<float2*>(&C[(size_t)mB*128 + n]) = make_float2(c10, c11);
        }
    }
}

// ---------------- fused attention, HEAD-SPLIT: block = (query bn, head-half hh) ----------------
// 4 heads per block, grid 1280; proj partial per half via atomicAdd into g_x.
__global__ __launch_bounds__(256, 6) void attn_kernel(
    const unsigned char* __restrict__ xmask,
    const unsigned char* __restrict__ lmask,
    const float* __restrict__ projw,
    const float* __restrict__ projb)
{
    int bn = blockIdx.x;                 // 0..639
    int hh = blockIdx.y;                 // head-half 0/1
    int b = bn / NN;
    int cb = hh * 64;                    // column base within 128
    int tid = threadIdx.x;

    __shared__ float s_s[4*SP];          // 5136 B
    __shared__ float ctxp[16][64];       // 4096 B
    __shared__ float ctx_s[64];
    __shared__ float prj[2][128];

    // ---- scores: thread (ml = tid>>2 -> 64 rows/chunk, hl = tid&3), 5 chunks ----
    {
        int ml = tid >> 2, hl = tid & 3;
        const uint4* qg = reinterpret_cast<const uint4*>(
            g_qh + (size_t)bn*128 + cb + hl*16);
        uint4 qa = qg[0], qb = qg[1];
        const __half2* q2a = reinterpret_cast<const __half2*>(&qa);
        const __half2* q2b = reinterpret_cast<const __half2*>(&qb);

        #pragma unroll
        for (int mc = 0; mc < NN; mc += 64) {
            int m = mc + ml;
            const uint4* kg = reinterpret_cast<const uint4*>(
                g_kvh + (size_t)(b*NN + m)*256 + cb + hl*16);
            uint4 ka = kg[0], kb_ = kg[1];
            uint4 ra = __ldcs(reinterpret_cast<const uint4*>(
                g_rp8 + ((size_t)bn*NN + m)*128 + cb + hl*16));
            const __half2* k2a = reinterpret_cast<const __half2*>(&ka);
            const __half2* k2b = reinterpret_cast<const __half2*>(&kb_);
            const __nv_fp8x2_storage_t* r8 =
                reinterpret_cast<const __nv_fp8x2_storage_t*>(&ra);
            __half2 acc_h = __floats2half2_rn(0.f, 0.f);
            #pragma unroll
            for (int j = 0; j < 4; j++) {
                acc_h = __hfma2(q2a[j], __hadd2(k2a[j], fp8x2_to_h2(r8[j])),   acc_h);
                acc_h = __hfma2(q2b[j], __hadd2(k2b[j], fp8x2_to_h2(r8[j+4])), acc_h);
            }
            float2 sf = __half22float2(acc_h);
            float s = (sf.x + sf.y) * 0.25f;
            bool pm = (m < NA) ? (xmask[b*NA + m] != 0)
                               : (lmask[b*NL + m - NA] != 0);
            if (pm) s = -1e9f;
            s_s[hl*SP + m] = s;
        }
    }
    __syncthreads();

    // ---- softmax: warps 0-3, one per local head ----
    if (tid < 128) {
        int h = tid >> 5, lane = tid & 31;
        float mx = -1e30f;
        for (int m = lane; m < NN; m += 32) mx = fmaxf(mx, s_s[h*SP + m]);
        #pragma unroll
        for (int o = 16; o; o >>= 1) mx = fmaxf(mx, __shfl_xor_sync(~0u, mx, o));
        float sum = 0.f;
        for (int m = lane; m < NN; m += 32) {
            float e = __expf(s_s[h*SP + m] - mx);
            s_s[h*SP + m] = e;
            sum += e;
        }
        #pragma unroll
        for (int o = 16; o; o >>= 1) sum += __shfl_xor_sync(~0u, sum, o);
        float inv = 1.f / sum;
        for (int m = lane; m < NN; m += 32) s_s[h*SP + m] *= inv;
    }
    __syncthreads();

    // ---- context: thread owns 8-half slice of 64 cols, 32 m-slices ----
    {
        int d8 = tid & 7, ms = tid >> 3;   // d8 0..7, ms 0..31
        int hl = d8 >> 1;
        float acc[8];
        #pragma unroll
        for (int j = 0; j < 8; j++) acc[j] = 0.f;
        #pragma unroll 2
        for (int m = ms; m < NN; m += 32) {
            float a = s_s[hl*SP + m];
            uint4 vv = *reinterpret_cast<const uint4*>(
                g_kvh + (size_t)(b*NN + m)*256 + 128 + cb + d8*8);
            uint2 rr = __ldcs(reinterpret_cast<const uint2*>(
                g_rpn8 + ((size_t)bn*NN + m)*128 + cb + d8*8));
            const __half2* v2 = reinterpret_cast<const __half2*>(&vv);
            const __nv_fp8x2_storage_t* r8 =
                reinterpret_cast<const __nv_fp8x2_storage_t*>(&rr);
            #pragma unroll
            for (int j = 0; j < 4; j++) {
                float2 s2 = __half22float2(__hadd2(v2[j], fp8x2_to_h2(r8[j])));
                acc[2*j    ] += a * s2.x;
                acc[2*j + 1] += a * s2.y;
            }
        }
        // two-stage reduce: slices 16..31 store, 0..15 accumulate
        if (ms >= 16) {
            #pragma unroll
            for (int j = 0; j < 8; j++) ctxp[ms - 16][d8*8 + j] = acc[j];
        }
        __syncthreads();
        if (ms < 16) {
            #pragma unroll
            for (int j = 0; j < 8; j++)
                ctxp[ms][d8*8 + j] += acc[j];
        }
    }
    __syncthreads();
    if (tid < 64) {
        float s = 0.f;
        #pragma unroll
        for (int j = 0; j < 16; j++) s += ctxp[j][tid];
        ctx_s[tid] = s;
    }
    __syncthreads();

    // ---- proj partial (this half's 64 d-rows) + atomic accumulate into g_x ----
    {
        int c = tid & 127, seg = tid >> 7;   // seg 0/1: 32 d each
        float acc = 0.f;
        #pragma unroll 8
        for (int j = 0; j < 32; j++) {
            int dl = seg*32 + j;
            acc += ctx_s[dl] * projw[(size_t)(cb + dl)*128 + c];
        }
        prj[seg][c] = acc;
    }
    __syncthreads();
    if (tid < 128) {
        float v = prj[0][tid] + prj[1][tid];
        if (hh == 0) v += projb[tid];
        atomicAdd(&g_x[(size_t)bn*128 + tid], v);
    }
}

// ---------------- launch ----------------
extern "C" void kernel_launch(void* const* d_in, const int* in_sizes, int n_in,
                              void* d_out, int out_size) {
    const float* agent = (const float*)d_in[0];
    const float* lane  = (const float*)d_in[1];
    const float* xpos  = (const float*)d_in[2];
    const float* xang  = (const float*)d_in[3];
    const float* lpos  = (const float*)d_in[4];
    const unsigned char* xmask = (const unsigned char*)d_in[5];
    const unsigned char* lmask = (const unsigned char*)d_in[6];
    const float* pw1 = (const float*)d_in[7];
    const float* pb1 = (const float*)d_in[8];
    const float* pw2 = (const float*)d_in[9];
    const float* pb2 = (const float*)d_in[10];
    const float* nw1 = (const float*)d_in[11];
    const float* nb1 = (const float*)d_in[12];
    const float* nw2 = (const float*)d_in[13];
    const float* nb2 = (const float*)d_in[14];
    const float* qkvw = (const float*)d_in[15];
    const float* qkvb = (const float*)d_in[16];
    const float* projw = (const float*)d_in[17];
    const float* projb = (const float*)d_in[18];
    const float* ln1g = (const float*)d_in[19];
    const float* ln1b = (const float*)d_in[20];
    const float* fc1w = (const float*)d_in[21];
    const float* fc1b = (const float*)d_in[22];
    const float* fc2w = (const float*)d_in[23];
    const float* fc2b = (const float*)d_in[24];
    const float* ln2g = (const float*)d_in[25];
    const float* ln2b = (const float*)d_in[26];

    float *px;
    cudaGetSymbolAddress((void**)&px, g_x);
    __half *pwT;
    cudaGetSymbolAddress((void**)&pwT, g_wT);

    prep_kernel<<<3 + 128 + 320 + 576 + 768 + 768, 256>>>(
        xpos, xang, lpos, pw2, nw2, agent, lane, qkvw, fc1w, fc2w);
    relmlp_kernel<<<dim3(NPAIR/128, 2), 512>>>(pw1, pb1, pb2, nw1, nb1, nb2);

    for (int i = 0; i < LL; i++) {
        gemmh<0><<<dim3(6, 20), 256>>>(
            px, pwT + (size_t)i*384*128, qkvb + i*384,
            ln1g + i*DD, ln1b + i*DD, nullptr, nullptr, 384);
        attn_kernel<<<dim3(BB*NN, 2), 256>>>(xmask, lmask,
                                             projw + (size_t)i*DD*DD, projb + i*DD);
        gemmh<1><<<dim3(8, 20), 256>>>(
            px, pwT + QKOFF + (size_t)i*512*128, fc1b + i*512,
            ln2g + i*DD, ln2b + i*DD, nullptr, nullptr, 512);
        float* outx = (i == LL-1) ? (float*)d_out : px;
        gemmh<2><<<dim3(2, 20), 256>>>(
            nullptr, pwT + FC2OFF + (size_t)i*128*512, fc2b + i*DD,
            nullptr, nullptr, px, outx, 128);
    }
}

// round 16
// speedup vs baseline: 1.1236x; 1.1236x over previous
#include <cuda_runtime.h>
#include <cuda_bf16.h>
#include <cuda_fp16.h>
#include <cuda_fp8.h>
#include <math.h>

// Problem constants
#define BB 2
#define NA 64
#define NL 256
#define NN 320          // N = NA + NL
#define DD 128
#define HH 8
#define HDD 16
#define LL 3
#define TT 50
#define NPAIR (BB*NN*NN)     // 204800
#define SP 321               // padded score stride (bank-conflict-free)

#define QKOFF  (3*384*128)                  // 147456
#define FC2OFF (QKOFF + 3*512*128)          // 344064
#define WTOT   (FC2OFF + 3*128*512)         // 540672

// ---------------- device scratch ----------------
__device__ float g_pf[BB*NN*3];
__device__ unsigned char g_rp8 [NPAIR*DD];  // rel_pos      fp8 e4m3
__device__ unsigned char g_rpn8[NPAIR*DD];  // rel_pos_neg  fp8 e4m3
__device__ __half g_w2t[2][DD*DD];    // relmlp W2^T fp16
__device__ __half g_wT[WTOT];         // qkv/fc1/fc2 weights, fp16, [n][k]
__device__ float g_x  [BB*NN*DD];
__device__ __half g_qh [BB*NN*DD];    // q fp16
__device__ __half g_kvh[BB*NN*256];   // k (0:128) | v (128:256) fp16
__device__ __half g_hidh[BB*NN*4*DD]; // fc1 hidden, fp16

__device__ __forceinline__ __half2 fp8x2_to_h2(__nv_fp8x2_storage_t v) {
    __half2_raw hr = __nv_cvt_fp8x2_to_halfraw2(v, __NV_E4M3);
    return *reinterpret_cast<__half2*>(&hr);
}

// ---------------- fused prep: pf + W2^T + initx + weightsT, one launch ----------------
__global__ void prep_kernel(const float* __restrict__ xpos,
                            const float* __restrict__ xang,
                            const float* __restrict__ lpos,
                            const float* __restrict__ pw2,
                            const float* __restrict__ nw2,
                            const float* __restrict__ agent,
                            const float* __restrict__ lane,
                            const float* __restrict__ qkvw,
                            const float* __restrict__ fc1w,
                            const float* __restrict__ fc2w) {
    int blk = blockIdx.x;
    int t = threadIdx.x;
    if (blk < 3) {                       // pose features: 640 items
        int i = blk * 256 + t;
        if (i >= BB*NN) return;
        int b = i / NN, n = i % NN;
        float px, py, pa;
        if (n < NA) {
            int base = ((b*NA + n)*TT + 49) * 2;
            px = xpos[base]; py = xpos[base+1];
            pa = xang[(b*NA + n)*TT + 49];
        } else {
            int l = n - NA;
            int base = (b*NL + l) * 20 * 2;
            px = lpos[base]; py = lpos[base+1];
            float x1 = lpos[base+2], y1 = lpos[base+3];
            pa = atan2f(y1 - py, x1 - px);
        }
        g_pf[i*3+0] = px; g_pf[i*3+1] = py; g_pf[i*3+2] = pa;
    } else if (blk < 3 + 128) {          // relmlp W2 transpose: 32768 items
        int idx = (blk - 3) * 256 + t;
        int s = idx >> 14;
        int r = idx & 16383;
        int n = r >> 7, k = r & 127;
        const float* W2 = s ? nw2 : pw2;
        g_w2t[s][n*DD + k] = __float2half(W2[k*DD + n]);
    } else if (blk < 3 + 128 + 320) {    // initx: 81920 items
        int i = (blk - 131) * 256 + t;
        if (i >= BB*NN*DD) return;
        int d = i & 127;
        int bn = i >> 7;
        int b = bn / NN, n = bn % NN;
        g_x[i] = (n < NA) ? agent[(b*NA + n)*DD + d]
                          : lane [(b*NL + (n - NA))*DD + d];
    } else if (blk < 451 + 576) {        // qkvw^T: 147456 items
        int idx = (blk - 451) * 256 + t;
        int l = idx / 49152, r = idx % 49152;
        int n = r >> 7, k = r & 127;
        g_wT[idx] = __float2half(qkvw[(size_t)l*49152 + k*384 + n]);
    } else if (blk < 451 + 576 + 768) {  // fc1w^T: 196608 items
        int idx = (blk - 1027) * 256 + t;
        int l = idx >> 16, r = idx & 65535;
        int n = r >> 7, k = r & 127;
        g_wT[QKOFF + idx] = __float2half(fc1w[(size_t)l*65536 + k*512 + n]);
    } else {                             // fc2w^T: 196608 items
        int idx = (blk - 1795) * 256 + t;
        int l = idx >> 16, r = idx & 65535;
        int n = r / 512, k = r % 512;
        g_wT[FC2OFF + idx] = __float2half(fc2w[(size_t)l*65536 + k*128 + n]);
    }
}

// ---------------- MMA / ldmatrix helpers ----------------
__device__ __forceinline__ void mma_f16(float& d0, float& d1, float& d2, float& d3,
                                        unsigned a0, unsigned a1, unsigned a2, unsigned a3,
                                        unsigned b0, unsigned b1) {
    asm volatile(
        "mma.sync.aligned.m16n8k16.row.col.f32.f16.f16.f32 "
        "{%0,%1,%2,%3}, {%4,%5,%6,%7}, {%8,%9}, {%0,%1,%2,%3};"
        : "+f"(d0), "+f"(d1), "+f"(d2), "+f"(d3)
        : "r"(a0), "r"(a1), "r"(a2), "r"(a3), "r"(b0), "r"(b1));
}

__device__ __forceinline__ void ldsm_x4(unsigned& d0, unsigned& d1,
                                        unsigned& d2, unsigned& d3, unsigned addr) {
    asm volatile("ldmatrix.sync.aligned.m8n8.x4.shared.b16 {%0,%1,%2,%3}, [%4];"
        : "=r"(d0), "=r"(d1), "=r"(d2), "=r"(d3) : "r"(addr));
}

__device__ __forceinline__ unsigned pack2(float lo, float hi) {
    __half2 h = __floats2half2_rn(lo, hi);
    return *reinterpret_cast<unsigned*>(&h);
}

// ---------------- rel-pos MLP: two-phase half2 hidden + fp16 MMA, fp8 output ----------------
// Register diet: ha[4][4] live per k-half (target <=64 regs -> 2 blocks/SM).
__global__ __launch_bounds__(512, 2) void relmlp_kernel(
    const float* __restrict__ pw1, const float* __restrict__ pb1,
    const float* __restrict__ pb2,
    const float* __restrict__ nw1, const float* __restrict__ nb1,
    const float* __restrict__ nb2)
{
    const int sign = blockIdx.y;                 // 0 = pos, 1 = neg
    const float* W1 = sign ? nw1 : pw1;
    const float* B1 = sign ? nb1 : pb1;
    const float* B2 = sign ? nb2 : pb2;
    unsigned char* out = sign ? g_rpn8 : g_rp8;

    __shared__ __half2 w1h[4][64];               // packed fp16 W1 [j][kpair]
    __shared__ __half2 b1h[64];
    __shared__ float b2_s[128];
    __shared__ float rel_s[128][4];
    __shared__ __half2 w2t_s[128][68];           // [n][kpair]; rows 272B, 16B-aligned

    int tid = threadIdx.x;
    int warp = tid >> 5, lane = tid & 31;
    int mg = warp >> 1, nh = warp & 1;
    int r0 = lane >> 2, cq = lane & 3;
    int mb = mg * 16;

    if (tid < 128) {
        b2_s[tid] = B2[tid];
        int p = blockIdx.x * 128 + tid;
        int b = p / (NN*NN);
        int r = p - b*(NN*NN);
        int n = r / NN;
        int m = r - n*NN;
        const float* pn = g_pf + (b*NN + n)*3;
        const float* pm = g_pf + (b*NN + m)*3;
        float dx = pn[0]-pm[0], dy = pn[1]-pm[1];
        float dist = sqrtf(dx*dx + dy*dy);
        float ad = pn[2]-pm[2];
        float sg = sign ? -1.f : 1.f;
        rel_s[tid][0] = sg*dx; rel_s[tid][1] = sg*dy;
        rel_s[tid][2] = dist;  rel_s[tid][3] = sg*ad;
    } else if (tid < 448) {
        int u = tid - 128;           // 0..319
        int j = u >> 6, t = u & 63;
        if (j < 4)
            w1h[j][t] = __floats2half2_rn(W1[j*128 + 2*t], W1[j*128 + 2*t + 1]);
        else
            b1h[t] = __floats2half2_rn(B1[2*t], B1[2*t + 1]);
    }
    {
        const uint4* src = reinterpret_cast<const uint4*>(&g_w2t[sign][0]);
        for (int idx = tid; idx < 2048; idx += 512) {
            int n = idx >> 4, c = idx & 15;
            *reinterpret_cast<uint4*>(&w2t_s[n][c*4]) = src[idx];
        }
    }
    __syncthreads();

    // rel features as half2 broadcasts for the two rows this lane owns
    __half2 rA[4], rB[4];
    #pragma unroll
    for (int j = 0; j < 4; j++) {
        rA[j] = __float2half2_rn(rel_s[mb + r0    ][j]);
        rB[j] = __float2half2_rn(rel_s[mb + r0 + 8][j]);
    }

    float acc[8][4];
    #pragma unroll
    for (int nt = 0; nt < 8; nt++)
        #pragma unroll
        for (int c = 0; c < 4; c++) acc[nt][c] = 0.f;

    unsigned lbase;
    {
        unsigned sb = (unsigned)__cvta_generic_to_shared(&w2t_s[0][0]);
        int rowt = nh*64 + ((lane >> 4) & 1)*8 + (lane & 7);
        lbase = sb + rowt*272 + ((lane >> 3) & 1)*16;
    }

    const __half2 zero2 = __floats2half2_rn(0.f, 0.f);
    // Two k-halves: ha[4][4] live at a time (register diet)
    #pragma unroll
    for (int hf = 0; hf < 2; hf++) {
        unsigned ha[4][4];
        #pragma unroll
        for (int s = 0; s < 4; s++) {
            int ss = hf*4 + s;
            #pragma unroll
            for (int pp = 0; pp < 2; pp++) {
                int t0 = ss*8 + pp*4 + cq;
                __half2 w0 = w1h[0][t0], w1v = w1h[1][t0],
                        w2v = w1h[2][t0], w3v = w1h[3][t0];
                __half2 hb = b1h[t0];
                __half2 hA = __hfma2(rA[0], w0, hb);
                hA = __hfma2(rA[1], w1v, hA);
                hA = __hfma2(rA[2], w2v, hA);
                hA = __hfma2(rA[3], w3v, hA);
                __half2 hB = __hfma2(rB[0], w0, hb);
                hB = __hfma2(rB[1], w1v, hB);
                hB = __hfma2(rB[2], w2v, hB);
                hB = __hfma2(rB[3], w3v, hB);
                hA = __hmax2(hA, zero2);
                hB = __hmax2(hB, zero2);
                ha[s][pp*2 + 0] = *reinterpret_cast<unsigned*>(&hA);
                ha[s][pp*2 + 1] = *reinterpret_cast<unsigned*>(&hB);
            }
        }
        #pragma unroll
        for (int s = 0; s < 4; s++) {
            int ss = hf*4 + s;
            #pragma unroll
            for (int g = 0; g < 4; g++) {
                unsigned b0, b1, b2v, b3;
                ldsm_x4(b0, b1, b2v, b3, lbase + g*(16*272) + ss*32);
                mma_f16(acc[2*g][0], acc[2*g][1], acc[2*g][2], acc[2*g][3],
                        ha[s][0], ha[s][1], ha[s][2], ha[s][3], b0, b1);
                mma_f16(acc[2*g+1][0], acc[2*g+1][1], acc[2*g+1][2], acc[2*g+1][3],
                        ha[s][0], ha[s][1], ha[s][2], ha[s][3], b2v, b3);
            }
        }
    }

    // epilogue: fp8-pack into reused smem, then bulk 16B stores
    __syncthreads();   // all MMA reads of w2t_s complete
    unsigned char* st8 = reinterpret_cast<unsigned char*>(w2t_s);
    #pragma unroll
    for (int nt = 0; nt < 8; nt++) {
        int col = nh*64 + nt*8 + 2*cq;
        float bi0 = b2_s[col], bi1 = b2_s[col+1];
        float2 f0 = make_float2(acc[nt][0] + bi0, acc[nt][1] + bi1);
        float2 f1 = make_float2(acc[nt][2] + bi0, acc[nt][3] + bi1);
        __nv_fp8x2_storage_t p0 = __nv_cvt_float2_to_fp8x2(f0, __NV_SATFINITE, __NV_E4M3);
        __nv_fp8x2_storage_t p1 = __nv_cvt_float2_to_fp8x2(f1, __NV_SATFINITE, __NV_E4M3);
        *reinterpret_cast<unsigned short*>(st8 + (mb + r0    )*128 + col) = p0;
        *reinterpret_cast<unsigned short*>(st8 + (mb + r0 + 8)*128 + col) = p1;
    }
    __syncthreads();
    {
        const uint4* src = reinterpret_cast<const uint4*>(st8);
        uint4* dst = reinterpret_cast<uint4*>(out + (size_t)blockIdx.x * 128 * 128);
        for (int idx = tid; idx < 1024; idx += 512)
            __stcs(dst + idx, src[idx]);
    }
}

// ---------------- fp16 tensor-core GEMM for the transformer chain ----------------
// MODE 0: qkv  = LN(A) @ W + b          -> g_qh / g_kvh (fp16)
// MODE 1: fc1  = relu(LN(A) @ W + b)    -> g_hidh (fp16)
// MODE 2: fc2  = g_hidh @ W + b + res   -> C (fp32), K=512
template<int MODE>
__global__ __launch_bounds__(256) void gemmh(
    const float* __restrict__ A, const __half* __restrict__ WT,
    const float* __restrict__ bias,
    const float* __restrict__ lng, const float* __restrict__ lnb,
    const float* __restrict__ res, float* __restrict__ C, int N)
{
    const int K = (MODE == 2) ? 512 : 128;
    __shared__ __half As_h[32][136];
    __shared__ __half Ws_h[64][136];
    __shared__ float bs_n[64];
    __shared__ float gs[128], bs[128];

    int tid = threadIdx.x;
    int warp = tid >> 5, lane = tid & 31;
    int r0 = lane >> 2, cq = lane & 3;
    int mg = warp >> 2, nh = warp & 3;
    int m0 = blockIdx.y * 32, n0 = blockIdx.x * 64;
    int mb = mg * 16;

    if (tid < 64) bs_n[tid] = bias[n0 + tid];
    if (MODE != 2 && tid >= 64 && tid < 192) {
        int t = tid - 64;
        gs[t] = lng[t]; bs[t] = lnb[t];
    }
    __syncthreads();

    float acc[2][4];
    #pragma unroll
    for (int nt = 0; nt < 2; nt++)
        #pragma unroll
        for (int c = 0; c < 4; c++) acc[nt][c] = 0.f;

    const int NCHUNK = (MODE == 2) ? 4 : 1;
    for (int kc = 0; kc < NCHUNK; kc++) {
        if (MODE == 2) {
            for (int idx = tid; idx < 512; idx += 256) {
                int row = idx >> 4, c = idx & 15;
                uint4 v = *reinterpret_cast<const uint4*>(
                    g_hidh + (size_t)(m0 + row)*512 + kc*128 + c*8);
                const __half2* h2 = reinterpret_cast<const __half2*>(&v);
                __half2* dst = reinterpret_cast<__half2*>(&As_h[row][c*8]);
                dst[0] = h2[0]; dst[1] = h2[1]; dst[2] = h2[2]; dst[3] = h2[3];
            }
        } else {
            #pragma unroll
            for (int r = 0; r < 4; r++) {
                int row = warp*4 + r;
                float4 v = *reinterpret_cast<const float4*>(
                    A + (size_t)(m0 + row)*128 + lane*4);
                float s = v.x + v.y + v.z + v.w;
                #pragma unroll
                for (int o = 16; o; o >>= 1) s += __shfl_xor_sync(~0u, s, o);
                float mu = s * 0.0078125f;
                float d0 = v.x-mu, d1 = v.y-mu, d2 = v.z-mu, d3 = v.w-mu;
                float q = d0*d0 + d1*d1 + d2*d2 + d3*d3;
                #pragma unroll
                for (int o = 16; o; o >>= 1) q += __shfl_xor_sync(~0u, q, o);
                float rs = rsqrtf(q * 0.0078125f + 1e-5f);
                int c0 = lane*4;
                float y0 = d0*rs*gs[c0  ] + bs[c0  ];
                float y1 = d1*rs*gs[c0+1] + bs[c0+1];
                float y2 = d2*rs*gs[c0+2] + bs[c0+2];
                float y3 = d3*rs*gs[c0+3] + bs[c0+3];
                __half2* dst = reinterpret_cast<__half2*>(&As_h[row][c0]);
                dst[0] = __floats2half2_rn(y0, y1);
                dst[1] = __floats2half2_rn(y2, y3);
            }
        }
        for (int idx = tid; idx < 1024; idx += 256) {
            int n = idx >> 4, c = idx & 15;
            uint4 v = *reinterpret_cast<const uint4*>(
                WT + (size_t)(n0 + n)*K + kc*128 + c*8);
            const __half2* h2 = reinterpret_cast<const __half2*>(&v);
            __half2* dst = reinterpret_cast<__half2*>(&Ws_h[n][c*8]);
            dst[0] = h2[0]; dst[1] = h2[1]; dst[2] = h2[2]; dst[3] = h2[3];
        }
        __syncthreads();

        #pragma unroll
        for (int s = 0; s < 8; s++) {
            unsigned a0 = *reinterpret_cast<unsigned*>(&As_h[mb+r0  ][16*s + 2*cq]);
            unsigned a1 = *reinterpret_cast<unsigned*>(&As_h[mb+r0+8][16*s + 2*cq]);
            unsigned a2 = *reinterpret_cast<unsigned*>(&As_h[mb+r0  ][16*s + 2*cq + 8]);
            unsigned a3 = *reinterpret_cast<unsigned*>(&As_h[mb+r0+8][16*s + 2*cq + 8]);
            #pragma unroll
            for (int nt = 0; nt < 2; nt++) {
                int n = nh*16 + nt*8 + r0;
                unsigned b0 = *reinterpret_cast<unsigned*>(&Ws_h[n][16*s + 2*cq]);
                unsigned b1 = *reinterpret_cast<unsigned*>(&Ws_h[n][16*s + 2*cq + 8]);
                mma_f16(acc[nt][0], acc[nt][1], acc[nt][2], acc[nt][3],
                        a0, a1, a2, a3, b0, b1);
            }
        }
        __syncthreads();
    }

    // ---- epilogue ----
    #pragma unroll
    for (int nt = 0; nt < 2; nt++) {
        int nloc = nh*16 + nt*8 + 2*cq;
        int n = n0 + nloc;
        float bi0 = bs_n[nloc], bi1 = bs_n[nloc+1];
        int mA = m0 + mb + r0, mB = mA + 8;
        float c00 = acc[nt][0] + bi0, c01 = acc[nt][1] + bi1;
        float c10 = acc[nt][2] + bi0, c11 = acc[nt][3] + bi1;
        if (MODE == 0) {
            int seg = n >> 7, off = n & 127;
            __half2 hA = __floats2half2_rn(c00, c01);
            __half2 hB = __floats2half2_rn(c10, c11);
            if (seg == 0) {
                *reinterpret_cast<__half2*>(&g_qh[(size_t)mA*128 + off]) = hA;
                *reinterpret_cast<__half2*>(&g_qh[(size_t)mB*128 + off]) = hB;
            } else if (seg == 1) {
                *reinterpret_cast<__half2*>(&g_kvh[(size_t)mA*256 + off]) = hA;
                *reinterpret_cast<__half2*>(&g_kvh[(size_t)mB*256 + off]) = hB;
            } else {
                *reinterpret_cast<__half2*>(&g_kvh[(size_t)mA*256 + 128 + off]) = hA;
                *reinterpret_cast<__half2*>(&g_kvh[(size_t)mB*256 + 128 + off]) = hB;
            }
        } else if (MODE == 1) {
            __half2 hA = __floats2half2_rn(fmaxf(c00, 0.f), fmaxf(c01, 0.f));
            __half2 hB = __floats2half2_rn(fmaxf(c10, 0.f), fmaxf(c11, 0.f));
            *reinterpret_cast<__half2*>(&g_hidh[(size_t)mA*512 + n]) = hA;
            *reinterpret_cast<__half2*>(&g_hidh[(size_t)mB*512 + n]) = hB;
        } else {
            c00 += res[(size_t)mA*128 + n];
            c01 += res[(size_t)mA*128 + n + 1];
            c10 += res[(size_t)mB*128 + n];
            c11 += res[(size_t)mB*128 + n + 1];
            *reinterpret_cast<float2*>(&C[(size_t)mA*128 + n]) = make_float2(c00, c01);
            *reinterpret_cast<float2*>(&C[(size_t)mB*128 + n]) = make_float2(c10, c11);
        }
    }
}

// ---------------- fused attention + proj + residual, 2 queries per block ----------------
// (round-14 configuration: best measured attn variant)
__global__ __launch_bounds__(256, 4) void attn_kernel(
    const unsigned char* __restrict__ xmask,
    const unsigned char* __restrict__ lmask,
    const float* __restrict__ projw,
    const float* __restrict__ projb)
{
    int bp = blockIdx.x;                 // 0..319
    int b = bp / (NN/2);
    int n0 = (bp % (NN/2)) * 2;
    size_t bn0 = (size_t)b*NN + n0;
    size_t bn1 = bn0 + 1;
    int tid = threadIdx.x;

    __shared__ float s_s[2][8*SP];    // 20544 B
    __shared__ float ctxp[8][128];    // 4096 B (reused per query)
    __shared__ float ctx_s[2][128];   // 1024 B

    // ---- scores for both queries ----
    {
        int ml = tid >> 3, h = tid & 7;
        const uint4* q0g = reinterpret_cast<const uint4*>(g_qh + bn0*128 + h*16);
        const uint4* q1g = reinterpret_cast<const uint4*>(g_qh + bn1*128 + h*16);
        uint4 q0a = q0g[0], q0b = q0g[1];
        uint4 q1a = q1g[0], q1b = q1g[1];
        const __half2* q0a2 = reinterpret_cast<const __half2*>(&q0a);
        const __half2* q0b2 = reinterpret_cast<const __half2*>(&q0b);
        const __half2* q1a2 = reinterpret_cast<const __half2*>(&q1a);
        const __half2* q1b2 = reinterpret_cast<const __half2*>(&q1b);

        for (int mc = 0; mc < NN; mc += 32) {
            int m = mc + ml;
            const uint4* kg = reinterpret_cast<const uint4*>(
                g_kvh + (size_t)(b*NN + m)*256 + h*16);
            uint4 ka = kg[0], kb_ = kg[1];
            uint4 r0v = __ldcs(reinterpret_cast<const uint4*>(
                g_rp8 + (bn0*NN + m)*128 + h*16));
            uint4 r1v = __ldcs(reinterpret_cast<const uint4*>(
                g_rp8 + (bn1*NN + m)*128 + h*16));
            const __half2* k2a = reinterpret_cast<const __half2*>(&ka);
            const __half2* k2b = reinterpret_cast<const __half2*>(&kb_);
            const __nv_fp8x2_storage_t* r08 =
                reinterpret_cast<const __nv_fp8x2_storage_t*>(&r0v);
            const __nv_fp8x2_storage_t* r18 =
                reinterpret_cast<const __nv_fp8x2_storage_t*>(&r1v);
            __half2 acc0 = __floats2half2_rn(0.f, 0.f);
            __half2 acc1 = __floats2half2_rn(0.f, 0.f);
            #pragma unroll
            for (int j = 0; j < 4; j++) {
                __half2 kja = k2a[j], kjb = k2b[j];
                acc0 = __hfma2(q0a2[j], __hadd2(kja, fp8x2_to_h2(r08[j])),   acc0);
                acc0 = __hfma2(q0b2[j], __hadd2(kjb, fp8x2_to_h2(r08[j+4])), acc0);
                acc1 = __hfma2(q1a2[j], __hadd2(kja, fp8x2_to_h2(r18[j])),   acc1);
                acc1 = __hfma2(q1b2[j], __hadd2(kjb, fp8x2_to_h2(r18[j+4])), acc1);
            }
            float2 s0f = __half22float2(acc0);
            float2 s1f = __half22float2(acc1);
            float s0 = (s0f.x + s0f.y) * 0.25f;
            float s1 = (s1f.x + s1f.y) * 0.25f;
            bool pm = (m < NA) ? (xmask[b*NA + m] != 0)
                               : (lmask[b*NL + m - NA] != 0);
            if (pm) { s0 = -1e9f; s1 = -1e9f; }
            s_s[0][h*SP + m] = s0;
            s_s[1][h*SP + m] = s1;
        }
    }
    __syncthreads();

    // ---- softmax: warp h handles head h for both queries ----
    {
        int h = tid >> 5, lane = tid & 31;
        #pragma unroll
        for (int qi = 0; qi < 2; qi++) {
            float* sr = &s_s[qi][h*SP];
            float mx = -1e30f;
            for (int m = lane; m < NN; m += 32) mx = fmaxf(mx, sr[m]);
            #pragma unroll
            for (int o = 16; o; o >>= 1) mx = fmaxf(mx, __shfl_xor_sync(~0u, mx, o));
            float sum = 0.f;
            for (int m = lane; m < NN; m += 32) {
                float e = __expf(sr[m] - mx);
                sr[m] = e;
                sum += e;
            }
            #pragma unroll
            for (int o = 16; o; o >>= 1) sum += __shfl_xor_sync(~0u, sum, o);
            float inv = 1.f / sum;
            for (int m = lane; m < NN; m += 32) sr[m] *= inv;
        }
    }
    __syncthreads();

    // ---- context for both queries: shared v loads ----
    {
        int d8 = tid & 15, ms = tid >> 4;
        int h = d8 >> 1;
        float a0c[8], a1c[8];
        #pragma unroll
        for (int j = 0; j < 8; j++) { a0c[j] = 0.f; a1c[j] = 0.f; }
        #pragma unroll 2
        for (int m = ms; m < NN; m += 16) {
            float a0 = s_s[0][h*SP + m];
            float a1 = s_s[1][h*SP + m];
            uint4 vv = *reinterpret_cast<const uint4*>(
                g_kvh + (size_t)(b*NN + m)*256 + 128 + d8*8);
            uint2 rr0 = __ldcs(reinterpret_cast<const uint2*>(
                g_rpn8 + (bn0*NN + m)*128 + d8*8));
            uint2 rr1 = __ldcs(reinterpret_cast<const uint2*>(
                g_rpn8 + (bn1*NN + m)*128 + d8*8));
            const __half2* v2 = reinterpret_cast<const __half2*>(&vv);
            const __nv_fp8x2_storage_t* r08 =
                reinterpret_cast<const __nv_fp8x2_storage_t*>(&rr0);
            const __nv_fp8x2_storage_t* r18 =
                reinterpret_cast<const __nv_fp8x2_storage_t*>(&rr1);
            #pragma unroll
            for (int j = 0; j < 4; j++) {
                __half2 vj = v2[j];
                float2 s20 = __half22float2(__hadd2(vj, fp8x2_to_h2(r08[j])));
                float2 s21 = __half22float2(__hadd2(vj, fp8x2_to_h2(r18[j])));
                a0c[2*j    ] += a0 * s20.x;
                a0c[2*j + 1] += a0 * s20.y;
                a1c[2*j    ] += a1 * s21.x;
                a1c[2*j + 1] += a1 * s21.y;
            }
        }
        // reduce query 0
        if (ms >= 8) {
            #pragma unroll
            for (int j = 0; j < 8; j++) ctxp[ms - 8][d8*8 + j] = a0c[j];
        }
        __syncthreads();
        if (ms < 8) {
            #pragma unroll
            for (int j = 0; j < 8; j++) ctxp[ms][d8*8 + j] += a0c[j];
        }
        __syncthreads();
        if (tid < 128) {
            float s = 0.f;
            #pragma unroll
            for (int j = 0; j < 8; j++) s += ctxp[j][tid];
            ctx_s[0][tid] = s;
        }
        __syncthreads();
        // reduce query 1
        if (ms >= 8) {
            #pragma unroll
            for (int j = 0; j < 8; j++) ctxp[ms - 8][d8*8 + j] = a1c[j];
        }
        __syncthreads();
        if (ms < 8) {
            #pragma unroll
            for (int j = 0; j < 8; j++) ctxp[ms][d8*8 + j] += a1c[j];
        }
        __syncthreads();
        if (tid < 128) {
            float s = 0.f;
            #pragma unroll
            for (int j = 0; j < 8; j++) s += ctxp[j][tid];
            ctx_s[1][tid] = s;
        }
    }
    __syncthreads();

    // ---- proj + residual: thread owns (query qi, column c) ----
    {
        int c = tid & 127, qi = tid >> 7;
        float acc = 0.f;
        #pragma unroll 8
        for (int d = 0; d < 128; d++)
            acc += ctx_s[qi][d] * projw[(size_t)d*128 + c];
        size_t row = qi ? bn1 : bn0;
        g_x[row*128 + c] += acc + projb[c];
    }
}

// ---------------- launch ----------------
extern "C" void kernel_launch(void* const* d_in, const int* in_sizes, int n_in,
                              void* d_out, int out_size) {
    const float* agent = (const float*)d_in[0];
    const float* lane  = (const float*)d_in[1];
    const float* xpos  = (const float*)d_in[2];
    const float* xang  = (const float*)d_in[3];
    const float* lpos  = (const float*)d_in[4];
    const unsigned char* xmask = (const unsigned char*)d_in[5];
    const unsigned char* lmask = (const unsigned char*)d_in[6];
    const float* pw1 = (const float*)d_in[7];
    const float* pb1 = (const float*)d_in[8];
    const float* pw2 = (const float*)d_in[9];
    const float* pb2 = (const float*)d_in[10];
    const float* nw1 = (const float*)d_in[11];
    const float* nb1 = (const float*)d_in[12];
    const float* nw2 = (const float*)d_in[13];
    const float* nb2 = (const float*)d_in[14];
    const float* qkvw = (const float*)d_in[15];
    const float* qkvb = (const float*)d_in[16];
    const float* projw = (const float*)d_in[17];
    const float* projb = (const float*)d_in[18];
    const float* ln1g = (const float*)d_in[19];
    const float* ln1b = (const float*)d_in[20];
    const float* fc1w = (const float*)d_in[21];
    const float* fc1b = (const float*)d_in[22];
    const float* fc2w = (const float*)d_in[23];
    const float* fc2b = (const float*)d_in[24];
    const float* ln2g = (const float*)d_in[25];
    const float* ln2b = (const float*)d_in[26];

    float *px;
    cudaGetSymbolAddress((void**)&px, g_x);
    __half *pwT;
    cudaGetSymbolAddress((void**)&pwT, g_wT);

    prep_kernel<<<3 + 128 + 320 + 576 + 768 + 768, 256>>>(
        xpos, xang, lpos, pw2, nw2, agent, lane, qkvw, fc1w, fc2w);
    relmlp_kernel<<<dim3(NPAIR/128, 2), 512>>>(pw1, pb1, pb2, nw1, nb1, nb2);

    for (int i = 0; i < LL; i++) {
        gemmh<0><<<dim3(6, 20), 256>>>(
            px, pwT + (size_t)i*384*128, qkvb + i*384,
            ln1g + i*DD, ln1b + i*DD, nullptr, nullptr, 384);
        attn_kernel<<<BB*NN/2, 256>>>(xmask, lmask,
                                      projw + (size_t)i*DD*DD, projb + i*DD);
        gemmh<1><<<dim3(8, 20), 256>>>(
            px, pwT + QKOFF + (size_t)i*512*128, fc1b + i*512,
            ln2g + i*DD, ln2b + i*DD, nullptr, nullptr, 512);
        float* outx = (i == LL-1) ? (float*)d_out : px;
        gemmh<2><<<dim3(2, 20), 256>>>(
            nullptr, pwT + FC2OFF + (size_t)i*128*512, fc2b + i*DD,
            nullptr, nullptr, px, outx, 128);
    }
}